// round 5
// baseline (speedup 1.0000x reference)
#include <cuda_runtime.h>
#include <cstddef>

// E=512, H=512, S=T=2048, NT=2
// Directions d: 0=src_fwd, 1=src_bwd, 2=tgt_fwd, 3=tgt_bwd

// ---------------- static device scratch ----------------
__device__ float  g_gx[4ll * 2048 * 1536];     // input gates (bih included by gemm)
__device__ float  g_ghn[4ll * 2048 * 512];     // n-gate partials (fallback path only)
__device__ float  g_src_out[2048ll * 1024];    // src BiGRU output [S, 2H]
__device__ float  g_tgt_out[2048ll * 1024];    // tgt BiGRU output [T, 2H]
__device__ float  g_align[2ll * 2048 * 2048];  // z=0 cross logits, z=1 self logits
__device__ int    g_cnt[4 * 2048];             // per (direction, step) counters (fallback)
__device__ float  g_y[3][4096];                // y1=tgt@W1^T, y2=src@W2^T, y3=tgt@W3^T [2048,2]
__device__ float  g_ctxE[2][4096];             // softmax-weighted y2 / y3 [2048,2]
__device__ float  g_emit[4096];                // emit [2048,2]
__device__ double g_matsA[2048 * 4];           // CRF log-semiring matrices
__device__ double g_matsB[2048 * 4];

struct P4 { const float* p[4]; };

typedef unsigned long long ull;

// ---------------- packed fp32x2 helpers (Blackwell fma.rn.f32x2) ----------------
#define FMA2(d, a, b, c) \
    asm("fma.rn.f32x2 %0, %1, %2, %3;" : "=l"(d) : "l"(a), "l"(b), "l"(c))

__device__ __forceinline__ ull pack2(float lo, float hi) {
    ull o;
    asm("mov.b64 %0, {%1, %2};" : "=l"(o)
        : "r"(__float_as_uint(lo)), "r"(__float_as_uint(hi)));
    return o;
}
__device__ __forceinline__ void unpack2(ull v, float& lo, float& hi) {
    unsigned int a, b;
    asm("mov.b64 {%0, %1}, %2;" : "=r"(a), "=r"(b) : "l"(v));
    lo = __uint_as_float(a); hi = __uint_as_float(b);
}

// ---------------- misc helpers ----------------
__device__ __forceinline__ int ldacq(const int* p) {
    int v;
    asm volatile("ld.acquire.gpu.b32 %0, [%1];" : "=r"(v) : "l"(p) : "memory");
    return v;
}
__device__ __forceinline__ void red_release_add(int* p) {
    asm volatile("red.release.gpu.global.add.u32 [%0], 1;" :: "l"(p) : "memory");
}
__device__ __forceinline__ double lse2d(double a, double b) {
    double m = fmax(a, b);
    double d = fmin(a, b) - m;   // <= 0
    return m + (double)log1pf(expf((float)d));
}
__device__ __forceinline__ float fast_sigmoid(float x) {
    return 1.0f / (1.0f + __expf(-x));
}
__device__ __forceinline__ float fast_tanh(float x) {
    float t = __expf(-2.0f * fabsf(x));  // in (0,1]
    float m = (1.0f - t) / (1.0f + t);
    return copysignf(m, x);
}
__device__ __forceinline__ unsigned int smem_u32(const void* p) {
    unsigned int a;
    asm("{ .reg .u64 t; cvta.to.shared.u64 t, %1; cvt.u32.u64 %0, t; }"
        : "=r"(a) : "l"(p));
    return a;
}

// ---------------- init (fallback path): zero n-partials + counters ----------------
__global__ __launch_bounds__(1024) void zero_kernel() {
    size_t i = (size_t)blockIdx.x * 1024 + threadIdx.x;
    g_ghn[i] = 0.0f;
    if (i < 4 * 2048) g_cnt[i] = 0;
}

// ---------------- generic NT GEMM (f32x2 packed): C = scale*(A@B^T)+bias -----------------
// 128x128 tile, BK=8, 256 threads, 8x8 per thread, double-buffered smem.
__device__ __forceinline__ void gemm_nt(
    const float* __restrict__ A, const float* __restrict__ B, float* __restrict__ C,
    int N, int K, const float* __restrict__ bias, float scale, bool diagmask)
{
    __shared__ __align__(16) float As[2][8][128];
    __shared__ __align__(16) float Bs[2][8][128];
    const int tid = threadIdx.x;
    const int lr = tid >> 1;            // 0..127: row within tile
    const int lk = (tid & 1) << 2;      // 0 or 4
    const float* Ag = A + (size_t)(blockIdx.y * 128 + lr) * K + lk;
    const float* Bg = B + (size_t)(blockIdx.x * 128 + lr) * K + lk;

    float4 a4 = *(const float4*)Ag;
    float4 b4 = *(const float4*)Bg;
    int buf = 0;
    As[0][lk + 0][lr] = a4.x; As[0][lk + 1][lr] = a4.y; As[0][lk + 2][lr] = a4.z; As[0][lk + 3][lr] = a4.w;
    Bs[0][lk + 0][lr] = b4.x; Bs[0][lk + 1][lr] = b4.y; Bs[0][lk + 2][lr] = b4.z; Bs[0][lk + 3][lr] = b4.w;
    __syncthreads();

    ull acc2[8][4];
#pragma unroll
    for (int i = 0; i < 8; i++)
#pragma unroll
        for (int j = 0; j < 4; j++) acc2[i][j] = 0ull;

    const int ty = tid >> 4, tx = tid & 15;
    const int ktiles = K >> 3;
    for (int kt = 1; kt <= ktiles; ++kt) {
        float4 na, nb;
        if (kt < ktiles) {
            na = *(const float4*)(Ag + kt * 8);
            nb = *(const float4*)(Bg + kt * 8);
        }
#pragma unroll
        for (int k = 0; k < 8; ++k) {
            float4 a0 = *(const float4*)&As[buf][k][ty * 8];
            float4 a1 = *(const float4*)&As[buf][k][ty * 8 + 4];
            ulonglong2 bq0 = *(const ulonglong2*)&Bs[buf][k][tx * 8];
            ulonglong2 bq1 = *(const ulonglong2*)&Bs[buf][k][tx * 8 + 4];
            ull rb2[4] = { bq0.x, bq0.y, bq1.x, bq1.y };
            ull ra2[8];
            ra2[0] = pack2(a0.x, a0.x); ra2[1] = pack2(a0.y, a0.y);
            ra2[2] = pack2(a0.z, a0.z); ra2[3] = pack2(a0.w, a0.w);
            ra2[4] = pack2(a1.x, a1.x); ra2[5] = pack2(a1.y, a1.y);
            ra2[6] = pack2(a1.z, a1.z); ra2[7] = pack2(a1.w, a1.w);
#pragma unroll
            for (int i = 0; i < 8; i++)
#pragma unroll
                for (int j = 0; j < 4; j++)
                    FMA2(acc2[i][j], ra2[i], rb2[j], acc2[i][j]);
        }
        if (kt < ktiles) {
            buf ^= 1;
            As[buf][lk + 0][lr] = na.x; As[buf][lk + 1][lr] = na.y; As[buf][lk + 2][lr] = na.z; As[buf][lk + 3][lr] = na.w;
            Bs[buf][lk + 0][lr] = nb.x; Bs[buf][lk + 1][lr] = nb.y; Bs[buf][lk + 2][lr] = nb.z; Bs[buf][lk + 3][lr] = nb.w;
            __syncthreads();
        }
    }

    const int gm0 = blockIdx.y * 128 + ty * 8;
    const int gn0 = blockIdx.x * 128 + tx * 8;
    float bv[8];
#pragma unroll
    for (int j = 0; j < 8; j++) bv[j] = bias ? bias[gn0 + j] : 0.0f;
#pragma unroll
    for (int i = 0; i < 8; i++) {
        int gm = gm0 + i;
        float o[8];
#pragma unroll
        for (int j = 0; j < 4; j++) unpack2(acc2[i][j], o[2 * j], o[2 * j + 1]);
#pragma unroll
        for (int j = 0; j < 8; j++) {
            o[j] = fmaf(o[j], scale, bv[j]);
            if (diagmask && gm == gn0 + j) o[j] = -1e30f;
        }
        float4* cp = (float4*)(C + (size_t)gm * N + gn0);
        cp[0] = make_float4(o[0], o[1], o[2], o[3]);
        cp[1] = make_float4(o[4], o[5], o[6], o[7]);
    }
}

__global__ __launch_bounds__(256) void gx_gemm_kernel(P4 xs, P4 wih, P4 bih) {
    int z = blockIdx.z;
    gemm_nt(xs.p[z], wih.p[z], g_gx + (size_t)z * 2048 * 1536, 1536, 512, bih.p[z], 1.0f, false);
}

__global__ __launch_bounds__(256) void logits_gemm_kernel() {
    int z = blockIdx.z;
    // temp = sqrt(1/(2H)) = 1/32 -> scale 32
    gemm_nt(g_tgt_out, z ? g_tgt_out : g_src_out,
            g_align + (size_t)z * 2048 * 2048, 2048, 1024, nullptr, 32.0f, z == 1);
}

// ============================================================================
// GRU recurrence — cluster/DSMEM version.
// One 16-CTA cluster per direction (grid 64, 512 thr). CTA rank owns h[32r..32r+32).
// Thread t owns gates r[t], z[t], n[t] (Whh rows t, 512+t, 1024+t), weight-stationary,
// cols [32*rank, 32*rank+32). Per step:
//   1. lanes<32 prefetch gx for current idx (consumed post-barrier)
//   2. packed-f32x2 partial dot over own 32 h
//   3. st.shared::cluster into owner CTA's slot [bank=s&1][g_local][my_rank]
//   4. barrier.cluster (release/acquire orders the DSMEM stores)
//   5. lanes<32 sum 16 slot values x3 gates (local LDS), activations, update h
//   6. __syncthreads (h visible for next step's partials)
// Slot WAR safety: reads of bank b at step s precede arrive(s+1); remote writes to
// bank b recur at step s+2, after wait(s+1). h WAR: all partial reads of hsm precede
// arrive(s); writes happen after wait(s).
// ============================================================================
__global__ __launch_bounds__(512, 1) __cluster_dims__(16, 1, 1)
void gru_cluster_kernel(P4 whh, P4 bhh) {
    const int d = blockIdx.x >> 4;
    unsigned int rank;
    asm("mov.u32 %0, %%cluster_ctarank;" : "=r"(rank));
    const int t = threadIdx.x;
    const bool rev = (d & 1) != 0;
    float* out = (d < 2) ? g_src_out : g_tgt_out;
    const int col = rev ? 512 : 0;
    const int J0 = (int)rank * 32;

    __shared__ __align__(16) float hsm[32];
    __shared__ __align__(16) float slots[2][96][16];

    // weight-stationary: 3 rows x 32 cols = 48 packed pairs
    const float* W = whh.p[d];
    ull wr2[16], wz2[16], wn2[16];
    {
        const ull* pr = (const ull*)(W + (size_t)t * 512 + J0);
        const ull* pz = (const ull*)(W + (size_t)(512 + t) * 512 + J0);
        const ull* pn = (const ull*)(W + (size_t)(1024 + t) * 512 + J0);
#pragma unroll
        for (int i = 0; i < 16; i++) { wr2[i] = pr[i]; wz2[i] = pz[i]; wn2[i] = pn[i]; }
    }

    float b_r = 0.f, b_z = 0.f, b_n = 0.f;
    if (t < 32) {
        const float* bh = bhh.p[d];
        b_r = bh[J0 + t]; b_z = bh[512 + J0 + t]; b_n = bh[1024 + J0 + t];
        hsm[t] = 0.0f;
    }
    __syncthreads();

    // remote slot base in owner CTA (gate owner = t>>5; g_local base = t&31)
    unsigned int slots_local = smem_u32(&slots[0][0][0]);
    unsigned int owner = (unsigned int)(t >> 5);
    unsigned int remote;
    asm("mapa.shared::cluster.u32 %0, %1, %2;" : "=r"(remote) : "r"(slots_local), "r"(owner));
    const unsigned int off_r = (unsigned int)(((t & 31) * 16 + (int)rank) * 4);
    const unsigned int bank_stride = 96 * 16 * 4;

    const float* gx = g_gx + (size_t)d * 2048 * 1536;
    float h = 0.0f;

    // align cluster before first stores
    asm volatile("barrier.cluster.arrive.aligned;" ::: "memory");
    asm volatile("barrier.cluster.wait.aligned;" ::: "memory");

    for (int s = 0; s < 2048; ++s) {
        const int idx = rev ? (2047 - s) : s;

        float gxr = 0.f, gxz = 0.f, gxn = 0.f;
        if (t < 32) {
            const float* gr = gx + (size_t)idx * 1536 + J0 + t;
            gxr = __ldcg(gr); gxz = __ldcg(gr + 512); gxn = __ldcg(gr + 1024);
        }

        // packed partial dot over this CTA's 32 h values
        ull accR = 0ull, accZ = 0ull, accN = 0ull;
        const ull* h2 = (const ull*)hsm;
#pragma unroll
        for (int i = 0; i < 16; i++) {
            ull hv = h2[i];
            FMA2(accR, wr2[i], hv, accR);
            FMA2(accZ, wz2[i], hv, accZ);
            FMA2(accN, wn2[i], hv, accN);
        }
        float lo, hi, ar, az, an;
        unpack2(accR, lo, hi); ar = lo + hi;
        unpack2(accZ, lo, hi); az = lo + hi;
        unpack2(accN, lo, hi); an = lo + hi;

        unsigned int base = remote + (unsigned int)(s & 1) * bank_stride + off_r;
        asm volatile("st.shared::cluster.f32 [%0], %1;" :: "r"(base), "f"(ar) : "memory");
        asm volatile("st.shared::cluster.f32 [%0], %1;" :: "r"(base + 32 * 16 * 4), "f"(az) : "memory");
        asm volatile("st.shared::cluster.f32 [%0], %1;" :: "r"(base + 64 * 16 * 4), "f"(an) : "memory");

        asm volatile("barrier.cluster.arrive.aligned;" ::: "memory");
        asm volatile("barrier.cluster.wait.aligned;" ::: "memory");

        if (t < 32) {
            const int bk = s & 1;
            const float4* pr4 = (const float4*)&slots[bk][t][0];
            const float4* pz4 = (const float4*)&slots[bk][32 + t][0];
            const float4* pn4 = (const float4*)&slots[bk][64 + t][0];
            float sr = 0.f, sz = 0.f, sn = 0.f;
#pragma unroll
            for (int q = 0; q < 4; q++) {
                float4 v;
                v = pr4[q]; sr += (v.x + v.y) + (v.z + v.w);
                v = pz4[q]; sz += (v.x + v.y) + (v.z + v.w);
                v = pn4[q]; sn += (v.x + v.y) + (v.z + v.w);
            }
            float r = fast_sigmoid(gxr + sr + b_r);
            float z = fast_sigmoid(gxz + sz + b_z);
            float n = fast_tanh(fmaf(r, sn + b_n, gxn));
            h = (1.0f - z) * n + z * h;
            hsm[t] = h;
            out[(size_t)idx * 1024 + col + J0 + t] = h;
        }
        __syncthreads();
    }
}

// ---------------- GRU recurrence (fallback, L2 atomics) — known-good ----------------
__global__ __launch_bounds__(512, 1) void gru_kernel(P4 whh, P4 bhh) {
    const int d = blockIdx.x >> 5;
    const int b = blockIdx.x & 31;
    const int tid = threadIdx.x;
    const bool rev = (d & 1) != 0;
    float* out = (d < 2) ? g_src_out : g_tgt_out;
    const int col = rev ? 512 : 0;
    const int J0 = b * 16;

    const float* W = whh.p[d];
    float wr[16], wz[16], wn[16];
#pragma unroll
    for (int q = 0; q < 4; q++) {
        float4 v;
        v = *(const float4*)(W + (size_t)tid * 512 + J0 + 4 * q);
        wr[4 * q + 0] = v.x; wr[4 * q + 1] = v.y; wr[4 * q + 2] = v.z; wr[4 * q + 3] = v.w;
        v = *(const float4*)(W + (size_t)(512 + tid) * 512 + J0 + 4 * q);
        wz[4 * q + 0] = v.x; wz[4 * q + 1] = v.y; wz[4 * q + 2] = v.z; wz[4 * q + 3] = v.w;
        v = *(const float4*)(W + (size_t)(1024 + tid) * 512 + J0 + 4 * q);
        wn[4 * q + 0] = v.x; wn[4 * q + 1] = v.y; wn[4 * q + 2] = v.z; wn[4 * q + 3] = v.w;
    }

    float b_r = 0.f, b_z = 0.f, b_n = 0.f;
    if (tid < 16) {
        const float* bh = bhh.p[d];
        b_r = bh[J0 + tid]; b_z = bh[512 + J0 + tid]; b_n = bh[1024 + J0 + tid];
    }

    __shared__ float hsm[16];
    if (tid < 16) hsm[tid] = 0.0f;
    __syncthreads();

    int* cnt = g_cnt + d * 2048;
    float* gx = g_gx + (size_t)d * 2048 * 1536;
    float* ghn = g_ghn + (size_t)d * 2048 * 512;

    float h0 = 0.f;

    for (int s = 0; s < 2048; ++s) {
        const int idx = rev ? (2047 - s) : s;
        float* rowRZ = gx + (size_t)idx * 1536;
        float* rowN  = ghn + (size_t)idx * 512;

        float ar = 0.f, az = 0.f, an = 0.f;
#pragma unroll
        for (int i = 0; i < 16; i++) {
            float hv = hsm[i];
            ar = fmaf(wr[i], hv, ar);
            az = fmaf(wz[i], hv, az);
            an = fmaf(wn[i], hv, an);
        }
        atomicAdd(rowRZ + tid, ar);
        atomicAdd(rowRZ + 512 + tid, az);
        atomicAdd(rowN + tid, an);

        __syncthreads();
        if (tid == 0) {
            red_release_add(cnt + s);
            while (ldacq(cnt + s) < 32) { }
        }
        __syncthreads();

        if (tid < 16) {
            const int j = J0 + tid;
            float sr  = __ldcg(rowRZ + j);
            float sz  = __ldcg(rowRZ + 512 + j);
            float gxn = __ldcg(rowRZ + 1024 + j);
            float anj = __ldcg(rowN + j);
            float r = fast_sigmoid(sr + b_r);
            float z = fast_sigmoid(sz + b_z);
            float n = fast_tanh(fmaf(r, anj + b_n, gxn));
            h0 = (1.0f - z) * n + z * h0;
            hsm[tid] = h0;
            out[(size_t)idx * 1024 + col + j] = h0;
        }
        __syncthreads();
    }
}

// ---------------- y projections: y[z][t,c] = A[t,:] . W_emit[c, z*1024 : z*1024+1024] ----------
__global__ __launch_bounds__(128) void y_kernel(const float* __restrict__ W_emit) {
    const int t = blockIdx.x, z = blockIdx.y;  // z: 0->y1(tgt), 1->y2(src), 2->y3(tgt)
    const float* A = (z == 1) ? g_src_out : g_tgt_out;
    const float* w0 = W_emit + z * 1024;
    const float* w1 = W_emit + 3072 + z * 1024;
    const float* a = A + (size_t)t * 1024;
    float s0 = 0.f, s1 = 0.f;
    for (int k = threadIdx.x; k < 1024; k += 128) {
        float av = a[k];
        s0 = fmaf(av, w0[k], s0);
        s1 = fmaf(av, w1[k], s1);
    }
#pragma unroll
    for (int o = 16; o > 0; o >>= 1) {
        s0 += __shfl_down_sync(0xffffffffu, s0, o);
        s1 += __shfl_down_sync(0xffffffffu, s1, o);
    }
    __shared__ float r0[4], r1[4];
    const int w = threadIdx.x >> 5, lane = threadIdx.x & 31;
    if (lane == 0) { r0[w] = s0; r1[w] = s1; }
    __syncthreads();
    if (threadIdx.x == 0) {
        g_y[z][t * 2 + 0] = r0[0] + r0[1] + r0[2] + r0[3];
        g_y[z][t * 2 + 1] = r1[0] + r1[1] + r1[2] + r1[3];
    }
}

// ---------------- fused softmax + weighted [.,2] reduction per row ----------------
__global__ __launch_bounds__(256) void softmax_kernel() {
    const int t = blockIdx.x, z = blockIdx.y;
    const float* L = g_align + (size_t)z * 2048 * 2048 + (size_t)t * 2048;
    const float* yv = g_y[z + 1];
    __shared__ float red[3][8];
    const int tid = threadIdx.x, w = tid >> 5, lane = tid & 31;

    float lv[8];
    float m = -1e30f;
#pragma unroll
    for (int i = 0; i < 8; i++) { lv[i] = L[tid + 256 * i]; m = fmaxf(m, lv[i]); }
#pragma unroll
    for (int o = 16; o > 0; o >>= 1) m = fmaxf(m, __shfl_xor_sync(0xffffffffu, m, o));
    if (lane == 0) red[0][w] = m;
    __syncthreads();
    m = fmaxf(fmaxf(fmaxf(red[0][0], red[0][1]), fmaxf(red[0][2], red[0][3])),
              fmaxf(fmaxf(red[0][4], red[0][5]), fmaxf(red[0][6], red[0][7])));
    __syncthreads();

    float Zs = 0.f, w0 = 0.f, w1 = 0.f;
#pragma unroll
    for (int i = 0; i < 8; i++) {
        int s = tid + 256 * i;
        float e = expf(lv[i] - m);
        Zs += e;
        w0 = fmaf(e, yv[s * 2 + 0], w0);
        w1 = fmaf(e, yv[s * 2 + 1], w1);
    }
#pragma unroll
    for (int o = 16; o > 0; o >>= 1) {
        Zs += __shfl_down_sync(0xffffffffu, Zs, o);
        w0 += __shfl_down_sync(0xffffffffu, w0, o);
        w1 += __shfl_down_sync(0xffffffffu, w1, o);
    }
    if (lane == 0) { red[0][w] = Zs; red[1][w] = w0; red[2][w] = w1; }
    __syncthreads();
    if (tid == 0) {
        float Z = 0.f, W0 = 0.f, W1 = 0.f;
#pragma unroll
        for (int q = 0; q < 8; q++) { Z += red[0][q]; W0 += red[1][q]; W1 += red[2][q]; }
        g_ctxE[z][t * 2 + 0] = W0 / Z;
        g_ctxE[z][t * 2 + 1] = W1 / Z;
    }
}

// ---------------- CRF: gold score + partition via parallel log-semiring scan ----------------
__global__ __launch_bounds__(1024) void crf_kernel(
    const int* __restrict__ labels, const float* __restrict__ b_emit,
    const float* __restrict__ t_start, const float* __restrict__ t_trans,
    const float* __restrict__ t_end, float* __restrict__ outp)
{
    const int tid = threadIdx.x;
    __shared__ double red[1024];
    __shared__ float tr[4];
    if (tid < 4) tr[tid] = t_trans[tid];
    __syncthreads();
    const float be0 = b_emit[0], be1 = b_emit[1];

    double acc = 0.0;
    for (int t = tid; t < 2048; t += 1024) {
        float e0 = g_y[0][t * 2 + 0] + g_ctxE[0][t * 2 + 0] + g_ctxE[1][t * 2 + 0] + be0;
        float e1 = g_y[0][t * 2 + 1] + g_ctxE[0][t * 2 + 1] + g_ctxE[1][t * 2 + 1] + be1;
        g_emit[t * 2 + 0] = e0;
        g_emit[t * 2 + 1] = e1;
        int lab = labels[t];
        acc += (double)(lab ? e1 : e0);
        if (t >= 1) {
            acc += (double)tr[lab * 2 + labels[t - 1]];
            double* M = g_matsA + (size_t)(t - 1) * 4;
            M[0] = (double)tr[0] + (double)e0;
            M[1] = (double)tr[1] + (double)e0;
            M[2] = (double)tr[2] + (double)e1;
            M[3] = (double)tr[3] + (double)e1;
        }
    }
    red[tid] = acc;
    __syncthreads();
    for (int o = 512; o > 0; o >>= 1) {
        if (tid < o) red[tid] += red[tid + o];
        __syncthreads();
    }

    double* A = g_matsA;
    double* B = g_matsB;
    int n = 2047;
    while (n > 1) {
        int m = n >> 1;
        for (int i = tid; i < m; i += 1024) {
            const double* Lm = A + (size_t)(2 * i + 1) * 4;
            const double* Rm = A + (size_t)(2 * i) * 4;
            double o0 = lse2d(Lm[0] + Rm[0], Lm[1] + Rm[2]);
            double o1 = lse2d(Lm[0] + Rm[1], Lm[1] + Rm[3]);
            double o2 = lse2d(Lm[2] + Rm[0], Lm[3] + Rm[2]);
            double o3 = lse2d(Lm[2] + Rm[1], Lm[3] + Rm[3]);
            double* O = B + (size_t)i * 4;
            O[0] = o0; O[1] = o1; O[2] = o2; O[3] = o3;
        }
        if ((n & 1) && tid == 0) {
#pragma unroll
            for (int q = 0; q < 4; q++) B[(size_t)m * 4 + q] = A[(size_t)(n - 1) * 4 + q];
        }
        n = m + (n & 1);
        __syncthreads();
        double* tp = A; A = B; B = tp;
    }

    if (tid == 0) {
        double gold = red[0] + (double)t_start[labels[0]] + (double)t_end[labels[2047]];
        double a0 = (double)t_start[0] + (double)g_emit[0];
        double a1 = (double)t_start[1] + (double)g_emit[1];
        const double* Pm = A;
        double aT0 = lse2d(Pm[0] + a0, Pm[1] + a1);
        double aT1 = lse2d(Pm[2] + a0, Pm[3] + a1);
        double logZ = lse2d((double)t_end[0] + aT0, (double)t_end[1] + aT1);
        outp[0] = (float)(gold - logZ);
    }
}

// ---------------- launch ----------------
extern "C" void kernel_launch(void* const* d_in, const int* in_sizes, int n_in,
                              void* d_out, int out_size) {
    const float* source  = (const float*)d_in[0];
    const float* target  = (const float*)d_in[1];
    const int*   labels  = (const int*)d_in[2];
    P4 xs, wih, whh, bih, bhh;
    for (int d = 0; d < 4; d++) {
        int base = 3 + 4 * d;
        wih.p[d] = (const float*)d_in[base + 0];
        whh.p[d] = (const float*)d_in[base + 1];
        bih.p[d] = (const float*)d_in[base + 2];
        bhh.p[d] = (const float*)d_in[base + 3];
        xs.p[d]  = (d < 2) ? source : target;
    }
    const float* W_emit  = (const float*)d_in[19];
    const float* b_emit  = (const float*)d_in[20];
    const float* t_start = (const float*)d_in[21];
    const float* t_trans = (const float*)d_in[22];
    const float* t_end   = (const float*)d_in[23];
    float* outp = (float*)d_out;

    // Non-portable 16-CTA cluster; deterministic fallback to the L2-atomics kernel.
    cudaError_t attrErr = cudaFuncSetAttribute(
        gru_cluster_kernel, cudaFuncAttributeNonPortableClusterSizeAllowed, 1);

    gx_gemm_kernel<<<dim3(12, 16, 4), 256>>>(xs, wih, bih);
    if (attrErr == cudaSuccess) {
        gru_cluster_kernel<<<64, 512>>>(whh, bhh);
    } else {
        zero_kernel<<<4096, 1024>>>();
        gru_kernel<<<128, 512>>>(whh, bhh);
    }
    logits_gemm_kernel<<<dim3(16, 16, 2), 256>>>();
    y_kernel<<<dim3(2048, 3), 128>>>(W_emit);
    softmax_kernel<<<dim3(2048, 2), 256>>>();
    crf_kernel<<<1, 1024>>>(labels, b_emit, t_start, t_trans, t_end, outp);
}

// round 8
// speedup vs baseline: 1.1357x; 1.1357x over previous
#include <cuda_runtime.h>
#include <cstddef>

// E=512, H=512, S=T=2048, NT=2
// Directions d: 0=src_fwd, 1=src_bwd, 2=tgt_fwd, 3=tgt_bwd

// ---------------- static device scratch ----------------
__device__ float  g_gx[4ll * 2048 * 1536];     // input gates; r/z cols double as atomic accumulators
__device__ float  g_ghn[4ll * 2048 * 512];     // n-gate hidden partial sums (atomic accumulators)
__device__ float  g_src_out[2048ll * 1024];    // src BiGRU output [S, 2H]
__device__ float  g_tgt_out[2048ll * 1024];    // tgt BiGRU output [T, 2H]
__device__ float  g_align[2ll * 2048 * 2048];  // z=0 cross logits, z=1 self logits
__device__ int    g_cnt[4 * 2048];             // per (direction, step) arrival counters
__device__ float  g_y[3][4096];                // y1=tgt@W1^T, y2=src@W2^T, y3=tgt@W3^T [2048,2]
__device__ float  g_ctxE[2][4096];             // softmax-weighted y2 / y3 [2048,2]
__device__ float  g_emit[4096];                // emit [2048,2]
__device__ double g_matsA[2048 * 4];           // CRF log-semiring matrices
__device__ double g_matsB[2048 * 4];

struct P4 { const float* p[4]; };

// ---------------- helpers ----------------
__device__ __forceinline__ int ldacq(const int* p) {
    int v;
    asm volatile("ld.acquire.gpu.b32 %0, [%1];" : "=r"(v) : "l"(p) : "memory");
    return v;
}
__device__ __forceinline__ void red_release_add(int* p) {
    asm volatile("red.release.gpu.global.add.u32 [%0], 1;" :: "l"(p) : "memory");
}
__device__ __forceinline__ double lse2d(double a, double b) {
    double m = fmax(a, b);
    double d = fmin(a, b) - m;   // <= 0
    return m + (double)log1pf(expf((float)d));
}
__device__ __forceinline__ float fast_sigmoid(float x) {
    return 1.0f / (1.0f + __expf(-x));
}
__device__ __forceinline__ float fast_tanh(float x) {
    float t = __expf(-2.0f * fabsf(x));  // in (0,1]
    float m = (1.0f - t) / (1.0f + t);
    return copysignf(m, x);
}

// ---------------- init: zero n-partials + counters ----------------
__global__ __launch_bounds__(1024) void zero_kernel() {
    size_t i = (size_t)blockIdx.x * 1024 + threadIdx.x;
    g_ghn[i] = 0.0f;                     // grid sized exactly 4*2048*512/1024
    if (i < 4 * 2048) g_cnt[i] = 0;
}

// ---------------- generic NT GEMM: C[M,N] = scale*(A[M,K] @ B[N,K]^T) + bias, opt diag mask ----
// 128x128 tile, BK=8, 256 threads, 8x8 per thread, double-buffered smem. (known-good scalar)
__device__ __forceinline__ void gemm_nt(
    const float* __restrict__ A, const float* __restrict__ B, float* __restrict__ C,
    int N, int K, const float* __restrict__ bias, float scale, bool diagmask)
{
    __shared__ __align__(16) float As[2][8][128];
    __shared__ __align__(16) float Bs[2][8][128];
    const int tid = threadIdx.x;
    const int lr = tid >> 1;            // 0..127: row within tile
    const int lk = (tid & 1) << 2;      // 0 or 4
    const float* Ag = A + (size_t)(blockIdx.y * 128 + lr) * K + lk;
    const float* Bg = B + (size_t)(blockIdx.x * 128 + lr) * K + lk;

    float4 a4 = *(const float4*)Ag;
    float4 b4 = *(const float4*)Bg;
    int buf = 0;
    As[0][lk + 0][lr] = a4.x; As[0][lk + 1][lr] = a4.y; As[0][lk + 2][lr] = a4.z; As[0][lk + 3][lr] = a4.w;
    Bs[0][lk + 0][lr] = b4.x; Bs[0][lk + 1][lr] = b4.y; Bs[0][lk + 2][lr] = b4.z; Bs[0][lk + 3][lr] = b4.w;
    __syncthreads();

    float acc[8][8];
#pragma unroll
    for (int i = 0; i < 8; i++)
#pragma unroll
        for (int j = 0; j < 8; j++) acc[i][j] = 0.0f;

    const int ty = tid >> 4, tx = tid & 15;
    const int ktiles = K >> 3;
    for (int kt = 1; kt <= ktiles; ++kt) {
        float4 na, nb;
        if (kt < ktiles) {
            na = *(const float4*)(Ag + kt * 8);
            nb = *(const float4*)(Bg + kt * 8);
        }
#pragma unroll
        for (int k = 0; k < 8; ++k) {
            float ra[8], rb[8];
            *(float4*)&ra[0] = *(const float4*)&As[buf][k][ty * 8];
            *(float4*)&ra[4] = *(const float4*)&As[buf][k][ty * 8 + 4];
            *(float4*)&rb[0] = *(const float4*)&Bs[buf][k][tx * 8];
            *(float4*)&rb[4] = *(const float4*)&Bs[buf][k][tx * 8 + 4];
#pragma unroll
            for (int i = 0; i < 8; i++)
#pragma unroll
                for (int j = 0; j < 8; j++) acc[i][j] = fmaf(ra[i], rb[j], acc[i][j]);
        }
        if (kt < ktiles) {
            buf ^= 1;
            As[buf][lk + 0][lr] = na.x; As[buf][lk + 1][lr] = na.y; As[buf][lk + 2][lr] = na.z; As[buf][lk + 3][lr] = na.w;
            Bs[buf][lk + 0][lr] = nb.x; Bs[buf][lk + 1][lr] = nb.y; Bs[buf][lk + 2][lr] = nb.z; Bs[buf][lk + 3][lr] = nb.w;
            __syncthreads();
        }
    }

    const int gm0 = blockIdx.y * 128 + ty * 8;
    const int gn0 = blockIdx.x * 128 + tx * 8;
    float bv[8];
#pragma unroll
    for (int j = 0; j < 8; j++) bv[j] = bias ? bias[gn0 + j] : 0.0f;
#pragma unroll
    for (int i = 0; i < 8; i++) {
        int gm = gm0 + i;
        float o[8];
#pragma unroll
        for (int j = 0; j < 8; j++) {
            o[j] = fmaf(acc[i][j], scale, bv[j]);
            if (diagmask && gm == gn0 + j) o[j] = -1e30f;
        }
        float4* cp = (float4*)(C + (size_t)gm * N + gn0);
        cp[0] = make_float4(o[0], o[1], o[2], o[3]);
        cp[1] = make_float4(o[4], o[5], o[6], o[7]);
    }
}

__global__ __launch_bounds__(256) void gx_gemm_kernel(P4 xs, P4 wih, P4 bih) {
    int z = blockIdx.z;
    gemm_nt(xs.p[z], wih.p[z], g_gx + (size_t)z * 2048 * 1536, 1536, 512, bih.p[z], 1.0f, false);
}

__global__ __launch_bounds__(256) void logits_gemm_kernel() {
    int z = blockIdx.z;
    // temp = sqrt(1/(2H)) = 1/32 -> scale 32
    gemm_nt(g_tgt_out, z ? g_tgt_out : g_src_out,
            g_align + (size_t)z * 2048 * 2048, 2048, 1024, nullptr, 32.0f, z == 1);
}

// ============================================================================
// GRU recurrence — paired directions. 64 CTAs x 512 threads.
// CTA (enc, b) owns h[16b..16b+16) for BOTH fwd (d=2*enc) and bwd (d=2*enc+1).
// Per step: fwd partials + REDs, bwd partials + REDs, one syncthreads, tid0
// releases both counters & polls fwd while tid32 (different warp) polls bwd;
// then lanes 0-15 (fwd) and threads 32-47 (bwd) run activations in parallel.
// The bwd rendezvous latency hides entirely inside the fwd one.
// ============================================================================
__global__ __launch_bounds__(512, 1) void gru_pair_kernel(P4 whh, P4 bhh) {
    const int enc = blockIdx.x >> 5;    // 0=src, 1=tgt
    const int b = blockIdx.x & 31;
    const int tid = threadIdx.x;
    const int dF = enc * 2, dB = dF + 1;
    float* out = enc ? g_tgt_out : g_src_out;
    const int J0 = b * 16;

    // Weight-stationary for both directions:
    // thread t holds rows t (r), 512+t (z), 1024+t (n), cols [J0, J0+16)
    const float* WF = whh.p[dF];
    const float* WB = whh.p[dB];
    float wrF[16], wzF[16], wnF[16], wrB[16], wzB[16], wnB[16];
#pragma unroll
    for (int q = 0; q < 4; q++) {
        float4 v;
        v = *(const float4*)(WF + (size_t)tid * 512 + J0 + 4 * q);
        wrF[4*q+0]=v.x; wrF[4*q+1]=v.y; wrF[4*q+2]=v.z; wrF[4*q+3]=v.w;
        v = *(const float4*)(WF + (size_t)(512 + tid) * 512 + J0 + 4 * q);
        wzF[4*q+0]=v.x; wzF[4*q+1]=v.y; wzF[4*q+2]=v.z; wzF[4*q+3]=v.w;
        v = *(const float4*)(WF + (size_t)(1024 + tid) * 512 + J0 + 4 * q);
        wnF[4*q+0]=v.x; wnF[4*q+1]=v.y; wnF[4*q+2]=v.z; wnF[4*q+3]=v.w;
        v = *(const float4*)(WB + (size_t)tid * 512 + J0 + 4 * q);
        wrB[4*q+0]=v.x; wrB[4*q+1]=v.y; wrB[4*q+2]=v.z; wrB[4*q+3]=v.w;
        v = *(const float4*)(WB + (size_t)(512 + tid) * 512 + J0 + 4 * q);
        wzB[4*q+0]=v.x; wzB[4*q+1]=v.y; wzB[4*q+2]=v.z; wzB[4*q+3]=v.w;
        v = *(const float4*)(WB + (size_t)(1024 + tid) * 512 + J0 + 4 * q);
        wnB[4*q+0]=v.x; wnB[4*q+1]=v.y; wnB[4*q+2]=v.z; wnB[4*q+3]=v.w;
    }

    // Activation-lane biases: lanes 0-15 -> fwd j=J0+tid; threads 32-47 -> bwd j=J0+tid-32
    float b_r = 0.f, b_z = 0.f, b_n = 0.f;
    if (tid < 16) {
        const float* bh = bhh.p[dF];
        b_r = bh[J0 + tid]; b_z = bh[512 + J0 + tid]; b_n = bh[1024 + J0 + tid];
    } else if (tid >= 32 && tid < 48) {
        const int j = J0 + tid - 32;
        const float* bh = bhh.p[dB];
        b_r = bh[j]; b_z = bh[512 + j]; b_n = bh[1024 + j];
    }

    __shared__ float hF[16], hB[16];
    if (tid < 16) { hF[tid] = 0.0f; hB[tid] = 0.0f; }
    __syncthreads();

    int* cntF = g_cnt + dF * 2048;
    int* cntB = g_cnt + dB * 2048;
    float* gxF  = g_gx  + (size_t)dF * 2048 * 1536;
    float* gxB  = g_gx  + (size_t)dB * 2048 * 1536;
    float* ghnF = g_ghn + (size_t)dF * 2048 * 512;
    float* ghnB = g_ghn + (size_t)dB * 2048 * 512;

    float h0 = 0.f;   // fwd h (lanes 0-15) / bwd h (threads 32-47)

    for (int s = 0; s < 2048; ++s) {
        const int idxF = s;
        const int idxB = 2047 - s;
        float* rowF  = gxF  + (size_t)idxF * 1536;
        float* rowNF = ghnF + (size_t)idxF * 512;
        float* rowB  = gxB  + (size_t)idxB * 1536;
        float* rowNB = ghnB + (size_t)idxB * 512;

        // ---- fwd partials + REDs ----
        {
            float ar = 0.f, az = 0.f, an = 0.f;
#pragma unroll
            for (int i = 0; i < 16; i++) {
                float hv = hF[i];
                ar = fmaf(wrF[i], hv, ar);
                az = fmaf(wzF[i], hv, az);
                an = fmaf(wnF[i], hv, an);
            }
            atomicAdd(rowF + tid, ar);
            atomicAdd(rowF + 512 + tid, az);
            atomicAdd(rowNF + tid, an);
        }
        // ---- bwd partials + REDs (issued while fwd REDs drain) ----
        {
            float ar = 0.f, az = 0.f, an = 0.f;
#pragma unroll
            for (int i = 0; i < 16; i++) {
                float hv = hB[i];
                ar = fmaf(wrB[i], hv, ar);
                az = fmaf(wzB[i], hv, az);
                an = fmaf(wnB[i], hv, an);
            }
            atomicAdd(rowB + tid, ar);
            atomicAdd(rowB + 512 + tid, az);
            atomicAdd(rowNB + tid, an);
        }

        __syncthreads();                  // all REDs of this CTA issued
        if (tid == 0) {
            red_release_add(cntF + s);    // release orders our REDs before count
            red_release_add(cntB + s);
            while (ldacq(cntF + s) < 32) { }
        } else if (tid == 32) {
            while (ldacq(cntB + s) < 32) { }   // parallel poll in warp 1
        }
        __syncthreads();                  // both directions' sums complete

        if (tid < 16) {                   // fwd activation
            const int j = J0 + tid;
            float sr  = __ldcg(rowF + j);
            float sz  = __ldcg(rowF + 512 + j);
            float gxn = __ldcg(rowF + 1024 + j);
            float anj = __ldcg(rowNF + j);
            float r = fast_sigmoid(sr + b_r);
            float z = fast_sigmoid(sz + b_z);
            float n = fast_tanh(fmaf(r, anj + b_n, gxn));
            h0 = (1.0f - z) * n + z * h0;
            hF[tid] = h0;
            out[(size_t)idxF * 1024 + j] = h0;                 // fwd -> cols [0,512)
        } else if (tid >= 32 && tid < 48) {   // bwd activation (parallel warp)
            const int j = J0 + tid - 32;
            float sr  = __ldcg(rowB + j);
            float sz  = __ldcg(rowB + 512 + j);
            float gxn = __ldcg(rowB + 1024 + j);
            float anj = __ldcg(rowNB + j);
            float r = fast_sigmoid(sr + b_r);
            float z = fast_sigmoid(sz + b_z);
            float n = fast_tanh(fmaf(r, anj + b_n, gxn));
            h0 = (1.0f - z) * n + z * h0;
            hB[tid - 32] = h0;
            out[(size_t)idxB * 1024 + 512 + j] = h0;           // bwd -> cols [512,1024)
        }
        __syncthreads();                  // new h slices visible for next step
    }
}

// ---------------- y projections: y[z][t,c] = A[t,:] . W_emit[c, z*1024 : z*1024+1024] ----------
__global__ __launch_bounds__(128) void y_kernel(const float* __restrict__ W_emit) {
    const int t = blockIdx.x, z = blockIdx.y;  // z: 0->y1(tgt), 1->y2(src), 2->y3(tgt)
    const float* A = (z == 1) ? g_src_out : g_tgt_out;
    const float* w0 = W_emit + z * 1024;
    const float* w1 = W_emit + 3072 + z * 1024;
    const float* a = A + (size_t)t * 1024;
    float s0 = 0.f, s1 = 0.f;
    for (int k = threadIdx.x; k < 1024; k += 128) {
        float av = a[k];
        s0 = fmaf(av, w0[k], s0);
        s1 = fmaf(av, w1[k], s1);
    }
#pragma unroll
    for (int o = 16; o > 0; o >>= 1) {
        s0 += __shfl_down_sync(0xffffffffu, s0, o);
        s1 += __shfl_down_sync(0xffffffffu, s1, o);
    }
    __shared__ float r0[4], r1[4];
    const int w = threadIdx.x >> 5, lane = threadIdx.x & 31;
    if (lane == 0) { r0[w] = s0; r1[w] = s1; }
    __syncthreads();
    if (threadIdx.x == 0) {
        g_y[z][t * 2 + 0] = r0[0] + r0[1] + r0[2] + r0[3];
        g_y[z][t * 2 + 1] = r1[0] + r1[1] + r1[2] + r1[3];
    }
}

// ---------------- fused softmax + weighted [.,2] reduction per row ----------------
__global__ __launch_bounds__(256) void softmax_kernel() {
    const int t = blockIdx.x, z = blockIdx.y;
    const float* L = g_align + (size_t)z * 2048 * 2048 + (size_t)t * 2048;
    const float* yv = g_y[z + 1];
    __shared__ float red[3][8];
    const int tid = threadIdx.x, w = tid >> 5, lane = tid & 31;

    float lv[8];
    float m = -1e30f;
#pragma unroll
    for (int i = 0; i < 8; i++) { lv[i] = L[tid + 256 * i]; m = fmaxf(m, lv[i]); }
#pragma unroll
    for (int o = 16; o > 0; o >>= 1) m = fmaxf(m, __shfl_xor_sync(0xffffffffu, m, o));
    if (lane == 0) red[0][w] = m;
    __syncthreads();
    m = fmaxf(fmaxf(fmaxf(red[0][0], red[0][1]), fmaxf(red[0][2], red[0][3])),
              fmaxf(fmaxf(red[0][4], red[0][5]), fmaxf(red[0][6], red[0][7])));
    __syncthreads();

    float Zs = 0.f, w0 = 0.f, w1 = 0.f;
#pragma unroll
    for (int i = 0; i < 8; i++) {
        int s = tid + 256 * i;
        float e = expf(lv[i] - m);
        Zs += e;
        w0 = fmaf(e, yv[s * 2 + 0], w0);
        w1 = fmaf(e, yv[s * 2 + 1], w1);
    }
#pragma unroll
    for (int o = 16; o > 0; o >>= 1) {
        Zs += __shfl_down_sync(0xffffffffu, Zs, o);
        w0 += __shfl_down_sync(0xffffffffu, w0, o);
        w1 += __shfl_down_sync(0xffffffffu, w1, o);
    }
    if (lane == 0) { red[0][w] = Zs; red[1][w] = w0; red[2][w] = w1; }
    __syncthreads();
    if (tid == 0) {
        float Z = 0.f, W0 = 0.f, W1 = 0.f;
#pragma unroll
        for (int q = 0; q < 8; q++) { Z += red[0][q]; W0 += red[1][q]; W1 += red[2][q]; }
        g_ctxE[z][t * 2 + 0] = W0 / Z;
        g_ctxE[z][t * 2 + 1] = W1 / Z;
    }
}

// ---------------- CRF: gold score + partition via parallel log-semiring scan ----------------
__global__ __launch_bounds__(1024) void crf_kernel(
    const int* __restrict__ labels, const float* __restrict__ b_emit,
    const float* __restrict__ t_start, const float* __restrict__ t_trans,
    const float* __restrict__ t_end, float* __restrict__ outp)
{
    const int tid = threadIdx.x;
    __shared__ double red[1024];
    __shared__ float tr[4];
    if (tid < 4) tr[tid] = t_trans[tid];
    __syncthreads();
    const float be0 = b_emit[0], be1 = b_emit[1];

    double acc = 0.0;
    for (int t = tid; t < 2048; t += 1024) {
        float e0 = g_y[0][t * 2 + 0] + g_ctxE[0][t * 2 + 0] + g_ctxE[1][t * 2 + 0] + be0;
        float e1 = g_y[0][t * 2 + 1] + g_ctxE[0][t * 2 + 1] + g_ctxE[1][t * 2 + 1] + be1;
        g_emit[t * 2 + 0] = e0;
        g_emit[t * 2 + 1] = e1;
        int lab = labels[t];
        acc += (double)(lab ? e1 : e0);
        if (t >= 1) {
            acc += (double)tr[lab * 2 + labels[t - 1]];
            double* M = g_matsA + (size_t)(t - 1) * 4;
            M[0] = (double)tr[0] + (double)e0;
            M[1] = (double)tr[1] + (double)e0;
            M[2] = (double)tr[2] + (double)e1;
            M[3] = (double)tr[3] + (double)e1;
        }
    }
    red[tid] = acc;
    __syncthreads();
    for (int o = 512; o > 0; o >>= 1) {
        if (tid < o) red[tid] += red[tid + o];
        __syncthreads();
    }

    double* A = g_matsA;
    double* B = g_matsB;
    int n = 2047;
    while (n > 1) {
        int m = n >> 1;
        for (int i = tid; i < m; i += 1024) {
            const double* Lm = A + (size_t)(2 * i + 1) * 4;
            const double* Rm = A + (size_t)(2 * i) * 4;
            double o0 = lse2d(Lm[0] + Rm[0], Lm[1] + Rm[2]);
            double o1 = lse2d(Lm[0] + Rm[1], Lm[1] + Rm[3]);
            double o2 = lse2d(Lm[2] + Rm[0], Lm[3] + Rm[2]);
            double o3 = lse2d(Lm[2] + Rm[1], Lm[3] + Rm[3]);
            double* O = B + (size_t)i * 4;
            O[0] = o0; O[1] = o1; O[2] = o2; O[3] = o3;
        }
        if ((n & 1) && tid == 0) {
#pragma unroll
            for (int q = 0; q < 4; q++) B[(size_t)m * 4 + q] = A[(size_t)(n - 1) * 4 + q];
        }
        n = m + (n & 1);
        __syncthreads();
        double* tp = A; A = B; B = tp;
    }

    if (tid == 0) {
        double gold = red[0] + (double)t_start[labels[0]] + (double)t_end[labels[2047]];
        double a0 = (double)t_start[0] + (double)g_emit[0];
        double a1 = (double)t_start[1] + (double)g_emit[1];
        const double* Pm = A;
        double aT0 = lse2d(Pm[0] + a0, Pm[1] + a1);
        double aT1 = lse2d(Pm[2] + a0, Pm[3] + a1);
        double logZ = lse2d((double)t_end[0] + aT0, (double)t_end[1] + aT1);
        outp[0] = (float)(gold - logZ);
    }
}

// ---------------- launch ----------------
extern "C" void kernel_launch(void* const* d_in, const int* in_sizes, int n_in,
                              void* d_out, int out_size) {
    const float* source  = (const float*)d_in[0];
    const float* target  = (const float*)d_in[1];
    const int*   labels  = (const int*)d_in[2];
    P4 xs, wih, whh, bih, bhh;
    for (int d = 0; d < 4; d++) {
        int base = 3 + 4 * d;
        wih.p[d] = (const float*)d_in[base + 0];
        whh.p[d] = (const float*)d_in[base + 1];
        bih.p[d] = (const float*)d_in[base + 2];
        bhh.p[d] = (const float*)d_in[base + 3];
        xs.p[d]  = (d < 2) ? source : target;
    }
    const float* W_emit  = (const float*)d_in[19];
    const float* b_emit  = (const float*)d_in[20];
    const float* t_start = (const float*)d_in[21];
    const float* t_trans = (const float*)d_in[22];
    const float* t_end   = (const float*)d_in[23];
    float* outp = (float*)d_out;

    zero_kernel<<<4096, 1024>>>();
    gx_gemm_kernel<<<dim3(12, 16, 4), 256>>>(xs, wih, bih);
    gru_pair_kernel<<<64, 512>>>(whh, bhh);
    logits_gemm_kernel<<<dim3(16, 16, 2), 256>>>();
    y_kernel<<<dim3(2048, 3), 128>>>(W_emit);
    softmax_kernel<<<dim3(2048, 2), 256>>>();
    crf_kernel<<<1, 1024>>>(labels, b_emit, t_start, t_trans, t_end, outp);
}

// round 9
// speedup vs baseline: 1.4811x; 1.3042x over previous
#include <cuda_runtime.h>
#include <cstddef>

// E=512, H=512, S=T=2048, NT=2
// Directions d: 0=src_fwd, 1=src_bwd, 2=tgt_fwd, 3=tgt_bwd

// ---------------- static device scratch ----------------
__device__ float  g_rz[4ll * 2048 * 1024];     // interleaved (r_j, z_j) gate accumulators (gx pre-added)
__device__ float  g_gn[4ll * 2048 * 512];      // n-gate input part (gx, read-only in GRU)
__device__ float  g_ghn[4ll * 2048 * 512];     // n-gate hidden partial sums (atomic accumulators)
__device__ float  g_src_out[2048ll * 1024];    // src BiGRU output [S, 2H]
__device__ float  g_tgt_out[2048ll * 1024];    // tgt BiGRU output [T, 2H]
__device__ float  g_align[2ll * 2048 * 2048];  // z=0 cross logits, z=1 self logits
__device__ int    g_cnt[4 * 2048];             // per (direction, step) arrival counters
__device__ float  g_y[3][4096];                // y1=tgt@W1^T, y2=src@W2^T, y3=tgt@W3^T [2048,2]
__device__ float  g_ctxE[2][4096];             // softmax-weighted y2 / y3 [2048,2]
__device__ float  g_emit[4096];                // emit [2048,2]
__device__ double g_matsA[2048 * 4];           // CRF log-semiring matrices
__device__ double g_matsB[2048 * 4];

struct P4 { const float* p[4]; };

typedef unsigned long long ull;

// ---------------- packed fp32x2 helpers (Blackwell fma.rn.f32x2) ----------------
#define FMA2(d, a, b, c) \
    asm("fma.rn.f32x2 %0, %1, %2, %3;" : "=l"(d) : "l"(a), "l"(b), "l"(c))

__device__ __forceinline__ ull pack2(float lo, float hi) {
    ull o;
    asm("mov.b64 %0, {%1, %2};" : "=l"(o)
        : "r"(__float_as_uint(lo)), "r"(__float_as_uint(hi)));
    return o;
}
__device__ __forceinline__ void unpack2(ull v, float& lo, float& hi) {
    unsigned int a, b;
    asm("mov.b64 {%0, %1}, %2;" : "=r"(a), "=r"(b) : "l"(v));
    lo = __uint_as_float(a); hi = __uint_as_float(b);
}

// ---------------- misc helpers ----------------
__device__ __forceinline__ int ldacq(const int* p) {
    int v;
    asm volatile("ld.acquire.gpu.b32 %0, [%1];" : "=r"(v) : "l"(p) : "memory");
    return v;
}
__device__ __forceinline__ void red_release_add(int* p) {
    asm volatile("red.release.gpu.global.add.u32 [%0], 1;" :: "l"(p) : "memory");
}
__device__ __forceinline__ double lse2d(double a, double b) {
    double m = fmax(a, b);
    double d = fmin(a, b) - m;   // <= 0
    return m + (double)log1pf(expf((float)d));
}
__device__ __forceinline__ float fast_sigmoid(float x) {
    return 1.0f / (1.0f + __expf(-x));
}
__device__ __forceinline__ float fast_tanh(float x) {
    float t = __expf(-2.0f * fabsf(x));  // in (0,1]
    float m = (1.0f - t) / (1.0f + t);
    return copysignf(m, x);
}

// ---------------- init: zero n-partials + counters ----------------
__global__ __launch_bounds__(1024) void zero_kernel() {
    size_t i = (size_t)blockIdx.x * 1024 + threadIdx.x;
    g_ghn[i] = 0.0f;                     // grid sized exactly 4*2048*512/1024
    if (i < 4 * 2048) g_cnt[i] = 0;
}

// ---------------- generic NT GEMM (f32x2 packed math) --------------------------------
// C[M,N] = scale*(A[M,K] @ B[N,K]^T) + bias.
// mode 0: contiguous float4 stores into C (logits path, optional diag mask).
// mode 1: gx path — scatter into interleaved rz buffer (C) / n buffer (C2) by gate type.
// 128x128 tile, BK=8, 256 threads, 8x8 per thread, double-buffered smem.
__device__ __forceinline__ void gemm_nt(
    const float* __restrict__ A, const float* __restrict__ B,
    float* __restrict__ C, float* __restrict__ C2,
    int N, int K, const float* __restrict__ bias, float scale,
    bool diagmask, int mode)
{
    __shared__ __align__(16) float As[2][8][128];
    __shared__ __align__(16) float Bs[2][8][128];
    const int tid = threadIdx.x;
    const int lr = tid >> 1;            // 0..127: row within tile
    const int lk = (tid & 1) << 2;      // 0 or 4
    const float* Ag = A + (size_t)(blockIdx.y * 128 + lr) * K + lk;
    const float* Bg = B + (size_t)(blockIdx.x * 128 + lr) * K + lk;

    float4 a4 = *(const float4*)Ag;
    float4 b4 = *(const float4*)Bg;
    int buf = 0;
    As[0][lk + 0][lr] = a4.x; As[0][lk + 1][lr] = a4.y; As[0][lk + 2][lr] = a4.z; As[0][lk + 3][lr] = a4.w;
    Bs[0][lk + 0][lr] = b4.x; Bs[0][lk + 1][lr] = b4.y; Bs[0][lk + 2][lr] = b4.z; Bs[0][lk + 3][lr] = b4.w;
    __syncthreads();

    ull acc2[8][4];
#pragma unroll
    for (int i = 0; i < 8; i++)
#pragma unroll
        for (int j = 0; j < 4; j++) acc2[i][j] = 0ull;

    const int ty = tid >> 4, tx = tid & 15;
    const int ktiles = K >> 3;
    for (int kt = 1; kt <= ktiles; ++kt) {
        float4 na, nb;
        if (kt < ktiles) {
            na = *(const float4*)(Ag + kt * 8);
            nb = *(const float4*)(Bg + kt * 8);
        }
#pragma unroll
        for (int k = 0; k < 8; ++k) {
            float4 a0 = *(const float4*)&As[buf][k][ty * 8];
            float4 a1 = *(const float4*)&As[buf][k][ty * 8 + 4];
            ulonglong2 bq0 = *(const ulonglong2*)&Bs[buf][k][tx * 8];
            ulonglong2 bq1 = *(const ulonglong2*)&Bs[buf][k][tx * 8 + 4];
            ull rb2[4] = { bq0.x, bq0.y, bq1.x, bq1.y };
            float av[8] = { a0.x, a0.y, a0.z, a0.w, a1.x, a1.y, a1.z, a1.w };
#pragma unroll
            for (int i = 0; i < 8; i++) {
                ull a2 = pack2(av[i], av[i]);
#pragma unroll
                for (int j = 0; j < 4; j++)
                    FMA2(acc2[i][j], a2, rb2[j], acc2[i][j]);
            }
        }
        if (kt < ktiles) {
            buf ^= 1;
            As[buf][lk + 0][lr] = na.x; As[buf][lk + 1][lr] = na.y; As[buf][lk + 2][lr] = na.z; As[buf][lk + 3][lr] = na.w;
            Bs[buf][lk + 0][lr] = nb.x; Bs[buf][lk + 1][lr] = nb.y; Bs[buf][lk + 2][lr] = nb.z; Bs[buf][lk + 3][lr] = nb.w;
            __syncthreads();
        }
    }

    const int gm0 = blockIdx.y * 128 + ty * 8;
    const int gn0 = blockIdx.x * 128 + tx * 8;
    float bv[8];
#pragma unroll
    for (int j = 0; j < 8; j++) bv[j] = bias ? bias[gn0 + j] : 0.0f;
#pragma unroll
    for (int i = 0; i < 8; i++) {
        int gm = gm0 + i;
        float o[8];
#pragma unroll
        for (int j = 0; j < 4; j++) unpack2(acc2[i][j], o[2 * j], o[2 * j + 1]);
#pragma unroll
        for (int j = 0; j < 8; j++) o[j] = fmaf(o[j], scale, bv[j]);

        if (mode == 0) {
#pragma unroll
            for (int j = 0; j < 8; j++)
                if (diagmask && gm == gn0 + j) o[j] = -1e30f;
            float4* cp = (float4*)(C + (size_t)gm * N + gn0);
            cp[0] = make_float4(o[0], o[1], o[2], o[3]);
            cp[1] = make_float4(o[4], o[5], o[6], o[7]);
        } else {
            // gx scatter: gate type uniform per block (128-col tiles within 512 blocks)
            if (gn0 < 512) {              // r -> rz[2*g]
#pragma unroll
                for (int j = 0; j < 8; j++)
                    C[(size_t)gm * 1024 + 2 * (gn0 + j)] = o[j];
            } else if (gn0 < 1024) {      // z -> rz[2*g+1]
#pragma unroll
                for (int j = 0; j < 8; j++)
                    C[(size_t)gm * 1024 + 2 * (gn0 - 512 + j) + 1] = o[j];
            } else {                      // n -> gn buffer
#pragma unroll
                for (int j = 0; j < 8; j++)
                    C2[(size_t)gm * 512 + (gn0 - 1024 + j)] = o[j];
            }
        }
    }
}

__global__ __launch_bounds__(256, 2) void gx_gemm_kernel(P4 xs, P4 wih, P4 bih) {
    int z = blockIdx.z;
    gemm_nt(xs.p[z], wih.p[z],
            g_rz + (size_t)z * 2048 * 1024, g_gn + (size_t)z * 2048 * 512,
            1536, 512, bih.p[z], 1.0f, false, 1);
}

__global__ __launch_bounds__(256, 2) void logits_gemm_kernel() {
    int z = blockIdx.z;
    // temp = sqrt(1/(2H)) = 1/32 -> scale 32
    gemm_nt(g_tgt_out, z ? g_tgt_out : g_src_out,
            g_align + (size_t)z * 2048 * 2048, nullptr,
            2048, 1024, nullptr, 32.0f, z == 1, 0);
}

// ============================================================================
// GRU recurrence — stationary-h outer-product (round-4 structure) with:
//   * interleaved rz accumulators -> ONE float2 atomicAdd for (r,z) per thread
//   * post-poll CTA barrier replaced by __syncwarp (activation is warp 0 only)
// Direction d: 32 CTAs; CTA b owns h[16b..16b+16). Thread t owns gate cols
// r[t], z[t] (one v2 RED into rz row) and n[t] (RED into ghn row).
// ============================================================================
__global__ __launch_bounds__(512, 1) void gru_kernel(P4 whh, P4 bhh) {
    const int d = blockIdx.x >> 5;
    const int b = blockIdx.x & 31;
    const int tid = threadIdx.x;
    const bool rev = (d & 1) != 0;
    float* out = (d < 2) ? g_src_out : g_tgt_out;
    const int col = rev ? 512 : 0;
    const int J0 = b * 16;

    // Weight-stationary: thread t holds Whh[t][J0..J0+16), Whh[512+t][...], Whh[1024+t][...]
    const float* W = whh.p[d];
    float wr[16], wz[16], wn[16];
#pragma unroll
    for (int q = 0; q < 4; q++) {
        float4 v;
        v = *(const float4*)(W + (size_t)tid * 512 + J0 + 4 * q);
        wr[4 * q + 0] = v.x; wr[4 * q + 1] = v.y; wr[4 * q + 2] = v.z; wr[4 * q + 3] = v.w;
        v = *(const float4*)(W + (size_t)(512 + tid) * 512 + J0 + 4 * q);
        wz[4 * q + 0] = v.x; wz[4 * q + 1] = v.y; wz[4 * q + 2] = v.z; wz[4 * q + 3] = v.w;
        v = *(const float4*)(W + (size_t)(1024 + tid) * 512 + J0 + 4 * q);
        wn[4 * q + 0] = v.x; wn[4 * q + 1] = v.y; wn[4 * q + 2] = v.z; wn[4 * q + 3] = v.w;
    }

    // Activation-lane constants (lanes 0..15 own h index j = J0 + tid)
    float b_r = 0.f, b_z = 0.f, b_n = 0.f;
    if (tid < 16) {
        const float* bh = bhh.p[d];
        b_r = bh[J0 + tid]; b_z = bh[512 + J0 + tid]; b_n = bh[1024 + J0 + tid];
    }

    __shared__ float hsm[16];
    if (tid < 16) hsm[tid] = 0.0f;
    __syncthreads();

    int* cnt = g_cnt + d * 2048;
    float* rz  = g_rz  + (size_t)d * 2048 * 1024;
    float* gnb = g_gn  + (size_t)d * 2048 * 512;
    float* ghn = g_ghn + (size_t)d * 2048 * 512;

    float h0 = 0.f;  // activation lane's current h value

    for (int s = 0; s < 2048; ++s) {
        const int idx = rev ? (2047 - s) : s;
        float* rowRZ = rz  + (size_t)idx * 1024;
        float* rowGN = gnb + (size_t)idx * 512;
        float* rowHN = ghn + (size_t)idx * 512;

        // outer-product partials: this CTA's 16 h values into gate columns `tid`
        float ar = 0.f, az = 0.f, an = 0.f;
#pragma unroll
        for (int i = 0; i < 16; i++) {
            float hv = hsm[i];
            ar = fmaf(wr[i], hv, ar);
            az = fmaf(wz[i], hv, az);
            an = fmaf(wn[i], hv, an);
        }
        atomicAdd((float2*)(rowRZ + 2 * tid), make_float2(ar, az));  // one 8B RED
        atomicAdd(rowHN + tid, an);

        __syncthreads();                 // all REDs of this CTA issued
        if (tid < 32) {
            if (tid == 0) {
                red_release_add(cnt + s);   // release: our REDs visible before count
                while (ldacq(cnt + s) < 32) { }
            }
            __syncwarp();                // fence: lanes see post-acquire state
            if (tid < 16) {
                const int j = J0 + tid;
                float2 srz = __ldcg((const float2*)(rowRZ + 2 * j));
                float gxn  = __ldcg(rowGN + j);
                float anj  = __ldcg(rowHN + j);
                float r = fast_sigmoid(srz.x + b_r);
                float z = fast_sigmoid(srz.y + b_z);
                float n = fast_tanh(fmaf(r, anj + b_n, gxn));
                h0 = (1.0f - z) * n + z * h0;
                hsm[tid] = h0;
                out[(size_t)idx * 1024 + col + j] = h0;
            }
        }
        __syncthreads();                 // new h slice visible for next step's FMAs
    }
}

// ---------------- y projections: y[z][t,c] = A[t,:] . W_emit[c, z*1024 : z*1024+1024] ----------
__global__ __launch_bounds__(128) void y_kernel(const float* __restrict__ W_emit) {
    const int t = blockIdx.x, z = blockIdx.y;  // z: 0->y1(tgt), 1->y2(src), 2->y3(tgt)
    const float* A = (z == 1) ? g_src_out : g_tgt_out;
    const float* w0 = W_emit + z * 1024;
    const float* w1 = W_emit + 3072 + z * 1024;
    const float* a = A + (size_t)t * 1024;
    float s0 = 0.f, s1 = 0.f;
    for (int k = threadIdx.x; k < 1024; k += 128) {
        float av = a[k];
        s0 = fmaf(av, w0[k], s0);
        s1 = fmaf(av, w1[k], s1);
    }
#pragma unroll
    for (int o = 16; o > 0; o >>= 1) {
        s0 += __shfl_down_sync(0xffffffffu, s0, o);
        s1 += __shfl_down_sync(0xffffffffu, s1, o);
    }
    __shared__ float r0[4], r1[4];
    const int w = threadIdx.x >> 5, lane = threadIdx.x & 31;
    if (lane == 0) { r0[w] = s0; r1[w] = s1; }
    __syncthreads();
    if (threadIdx.x == 0) {
        g_y[z][t * 2 + 0] = r0[0] + r0[1] + r0[2] + r0[3];
        g_y[z][t * 2 + 1] = r1[0] + r1[1] + r1[2] + r1[3];
    }
}

// ---------------- fused softmax + weighted [.,2] reduction per row ----------------
__global__ __launch_bounds__(256) void softmax_kernel() {
    const int t = blockIdx.x, z = blockIdx.y;
    const float* L = g_align + (size_t)z * 2048 * 2048 + (size_t)t * 2048;
    const float* yv = g_y[z + 1];
    __shared__ float red[3][8];
    const int tid = threadIdx.x, w = tid >> 5, lane = tid & 31;

    float lv[8];
    float m = -1e30f;
#pragma unroll
    for (int i = 0; i < 8; i++) { lv[i] = L[tid + 256 * i]; m = fmaxf(m, lv[i]); }
#pragma unroll
    for (int o = 16; o > 0; o >>= 1) m = fmaxf(m, __shfl_xor_sync(0xffffffffu, m, o));
    if (lane == 0) red[0][w] = m;
    __syncthreads();
    m = fmaxf(fmaxf(fmaxf(red[0][0], red[0][1]), fmaxf(red[0][2], red[0][3])),
              fmaxf(fmaxf(red[0][4], red[0][5]), fmaxf(red[0][6], red[0][7])));
    __syncthreads();

    float Zs = 0.f, w0 = 0.f, w1 = 0.f;
#pragma unroll
    for (int i = 0; i < 8; i++) {
        int s = tid + 256 * i;
        float e = expf(lv[i] - m);
        Zs += e;
        w0 = fmaf(e, yv[s * 2 + 0], w0);
        w1 = fmaf(e, yv[s * 2 + 1], w1);
    }
#pragma unroll
    for (int o = 16; o > 0; o >>= 1) {
        Zs += __shfl_down_sync(0xffffffffu, Zs, o);
        w0 += __shfl_down_sync(0xffffffffu, w0, o);
        w1 += __shfl_down_sync(0xffffffffu, w1, o);
    }
    if (lane == 0) { red[0][w] = Zs; red[1][w] = w0; red[2][w] = w1; }
    __syncthreads();
    if (tid == 0) {
        float Z = 0.f, W0 = 0.f, W1 = 0.f;
#pragma unroll
        for (int q = 0; q < 8; q++) { Z += red[0][q]; W0 += red[1][q]; W1 += red[2][q]; }
        g_ctxE[z][t * 2 + 0] = W0 / Z;
        g_ctxE[z][t * 2 + 1] = W1 / Z;
    }
}

// ---------------- CRF: gold score + partition via parallel log-semiring scan ----------------
__global__ __launch_bounds__(1024) void crf_kernel(
    const int* __restrict__ labels, const float* __restrict__ b_emit,
    const float* __restrict__ t_start, const float* __restrict__ t_trans,
    const float* __restrict__ t_end, float* __restrict__ outp)
{
    const int tid = threadIdx.x;
    __shared__ double red[1024];
    __shared__ float tr[4];
    if (tid < 4) tr[tid] = t_trans[tid];
    __syncthreads();
    const float be0 = b_emit[0], be1 = b_emit[1];

    double acc = 0.0;
    for (int t = tid; t < 2048; t += 1024) {
        float e0 = g_y[0][t * 2 + 0] + g_ctxE[0][t * 2 + 0] + g_ctxE[1][t * 2 + 0] + be0;
        float e1 = g_y[0][t * 2 + 1] + g_ctxE[0][t * 2 + 1] + g_ctxE[1][t * 2 + 1] + be1;
        g_emit[t * 2 + 0] = e0;
        g_emit[t * 2 + 1] = e1;
        int lab = labels[t];
        acc += (double)(lab ? e1 : e0);
        if (t >= 1) {
            acc += (double)tr[lab * 2 + labels[t - 1]];
            double* M = g_matsA + (size_t)(t - 1) * 4;
            M[0] = (double)tr[0] + (double)e0;
            M[1] = (double)tr[1] + (double)e0;
            M[2] = (double)tr[2] + (double)e1;
            M[3] = (double)tr[3] + (double)e1;
        }
    }
    red[tid] = acc;
    __syncthreads();
    for (int o = 512; o > 0; o >>= 1) {
        if (tid < o) red[tid] += red[tid + o];
        __syncthreads();
    }

    double* A = g_matsA;
    double* B = g_matsB;
    int n = 2047;
    while (n > 1) {
        int m = n >> 1;
        for (int i = tid; i < m; i += 1024) {
            const double* Lm = A + (size_t)(2 * i + 1) * 4;
            const double* Rm = A + (size_t)(2 * i) * 4;
            double o0 = lse2d(Lm[0] + Rm[0], Lm[1] + Rm[2]);
            double o1 = lse2d(Lm[0] + Rm[1], Lm[1] + Rm[3]);
            double o2 = lse2d(Lm[2] + Rm[0], Lm[3] + Rm[2]);
            double o3 = lse2d(Lm[2] + Rm[1], Lm[3] + Rm[3]);
            double* O = B + (size_t)i * 4;
            O[0] = o0; O[1] = o1; O[2] = o2; O[3] = o3;
        }
        if ((n & 1) && tid == 0) {
#pragma unroll
            for (int q = 0; q < 4; q++) B[(size_t)m * 4 + q] = A[(size_t)(n - 1) * 4 + q];
        }
        n = m + (n & 1);
        __syncthreads();
        double* tp = A; A = B; B = tp;
    }

    if (tid == 0) {
        double gold = red[0] + (double)t_start[labels[0]] + (double)t_end[labels[2047]];
        double a0 = (double)t_start[0] + (double)g_emit[0];
        double a1 = (double)t_start[1] + (double)g_emit[1];
        const double* Pm = A;
        double aT0 = lse2d(Pm[0] + a0, Pm[1] + a1);
        double aT1 = lse2d(Pm[2] + a0, Pm[3] + a1);
        double logZ = lse2d((double)t_end[0] + aT0, (double)t_end[1] + aT1);
        outp[0] = (float)(gold - logZ);
    }
}

// ---------------- launch ----------------
extern "C" void kernel_launch(void* const* d_in, const int* in_sizes, int n_in,
                              void* d_out, int out_size) {
    const float* source  = (const float*)d_in[0];
    const float* target  = (const float*)d_in[1];
    const int*   labels  = (const int*)d_in[2];
    P4 xs, wih, whh, bih, bhh;
    for (int d = 0; d < 4; d++) {
        int base = 3 + 4 * d;
        wih.p[d] = (const float*)d_in[base + 0];
        whh.p[d] = (const float*)d_in[base + 1];
        bih.p[d] = (const float*)d_in[base + 2];
        bhh.p[d] = (const float*)d_in[base + 3];
        xs.p[d]  = (d < 2) ? source : target;
    }
    const float* W_emit  = (const float*)d_in[19];
    const float* b_emit  = (const float*)d_in[20];
    const float* t_start = (const float*)d_in[21];
    const float* t_trans = (const float*)d_in[22];
    const float* t_end   = (const float*)d_in[23];
    float* outp = (float*)d_out;

    zero_kernel<<<4096, 1024>>>();
    gx_gemm_kernel<<<dim3(12, 16, 4), 256>>>(xs, wih, bih);
    gru_kernel<<<128, 512>>>(whh, bhh);
    logits_gemm_kernel<<<dim3(16, 16, 2), 256>>>();
    y_kernel<<<dim3(2048, 3), 128>>>(W_emit);
    softmax_kernel<<<dim3(2048, 2), 256>>>();
    crf_kernel<<<1, 1024>>>(labels, b_emit, t_start, t_trans, t_end, outp);
}